// round 11
// baseline (speedup 1.0000x reference)
#include <cuda_runtime.h>
#include <cuda_bf16.h>
#include <cstdint>

#define B_    16
#define CIN   32
#define COUT  32
#define H_    256
#define W_    256
#define HW    (H_ * W_)

__device__ float g_bfinal[B_ * COUT];
// B fragments: [b][g=tap*2+ks (18)][fp (4)][lane (32)] uint4 = frag pair
__device__ uint4 g_bfrag4[B_ * 18 * 4 * 32];

// ---------------------------------------------------------------------------
// PTX helpers (generic, sm_80+)
// ---------------------------------------------------------------------------
__device__ __forceinline__ uint32_t smem_u32(const void* p) {
    uint32_t a;
    asm("{ .reg .u64 t; cvta.to.shared.u64 t, %1; cvt.u32.u64 %0, t; }"
        : "=r"(a) : "l"(p));
    return a;
}
__device__ __forceinline__ void ldsm4(uint32_t* r, uint32_t a) {
    asm volatile("ldmatrix.sync.aligned.m8n8.x4.shared.b16 {%0,%1,%2,%3}, [%4];"
                 : "=r"(r[0]), "=r"(r[1]), "=r"(r[2]), "=r"(r[3]) : "r"(a));
}
__device__ __forceinline__ void ldsm2(uint32_t* r, uint32_t a) {
    asm volatile("ldmatrix.sync.aligned.m8n8.x2.shared.b16 {%0,%1}, [%2];"
                 : "=r"(r[0]), "=r"(r[1]) : "r"(a));
}
__device__ __forceinline__ void mma16816(float* d, const uint32_t* a,
                                         uint32_t b0, uint32_t b1) {
    asm volatile(
        "mma.sync.aligned.m16n8k16.row.col.f32.bf16.bf16.f32 "
        "{%0,%1,%2,%3}, {%4,%5,%6,%7}, {%8,%9}, {%0,%1,%2,%3};"
        : "+f"(d[0]), "+f"(d[1]), "+f"(d[2]), "+f"(d[3])
        : "r"(a[0]), "r"(a[1]), "r"(a[2]), "r"(a[3]), "r"(b0), "r"(b1));
}
__device__ __forceinline__ uint32_t pack_bf2(__nv_bfloat16 a, __nv_bfloat16 b) {
    return (uint32_t)__bfloat16_as_ushort(a) |
           ((uint32_t)__bfloat16_as_ushort(b) << 16);
}

// ---------------------------------------------------------------------------
// Prep kernel: grid (9 taps, 16 batches), 128 thr.
// ---------------------------------------------------------------------------
__global__ void __launch_bounds__(128)
prep_kernel(const float* __restrict__ cond,
            const float* __restrict__ lpe,
            const float* __restrict__ wa_w,
            const float* __restrict__ wa_b,
            const float* __restrict__ ba_w,
            const float* __restrict__ ba_b,
            const float* __restrict__ bias,
            const float* __restrict__ weights) {
    __shared__ float ivec[512];
    __shared__ float wad[CIN];
    __shared__ char  smB[32 * 128];

    const int tid  = threadIdx.x;
    const int warp = tid >> 5;
    const int lane = tid & 31;
    const int kl   = blockIdx.x;
    const int b    = blockIdx.y;

#pragma unroll
    for (int k = 0; k < 4; k++) {
        int idx = tid + 128 * k;
        ivec[idx] = (idx < 256) ? cond[b * 256 + idx] : lpe[b * 256 + idx - 256];
    }
    __syncthreads();

    for (int d = warp; d < 32; d += 4) {
        const float* wr = wa_w + d * 512;
        float s = 0.f;
#pragma unroll
        for (int k = lane; k < 512; k += 32) s += ivec[k] * wr[k];
#pragma unroll
        for (int off = 16; off; off >>= 1) s += __shfl_xor_sync(0xffffffffu, s, off);
        if (lane == 0) wad[d] = s + wa_b[d];
    }
    if (kl == 0) {
        for (int d = warp; d < 32; d += 4) {
            const float* wr = ba_w + d * 512;
            float s = 0.f;
#pragma unroll
            for (int k = lane; k < 512; k += 32) s += ivec[k] * wr[k];
#pragma unroll
            for (int off = 16; off; off >>= 1) s += __shfl_xor_sync(0xffffffffu, s, off);
            if (lane == 0) g_bfinal[b * COUT + d] = bias[d] * (s + ba_b[d]);
        }
    }
    __syncthreads();

    for (int e = tid; e < 32 * 32; e += 128) {
        int ci = e >> 5;
        int o  = e & 31;
        float v = weights[(ci * 32 + o) * 9 + kl] * wad[ci];
        __nv_bfloat16 h = __float2bfloat16(v);
        __nv_bfloat16 l = __float2bfloat16(v - __bfloat162float(h));
        int ch = (ci >> 3) ^ (o & 7);
        int cl = (4 + (ci >> 3)) ^ (o & 7);
        int wb = (ci & 7) * 2;
        *(__nv_bfloat16*)(smB + o * 128 + ch * 16 + wb) = h;
        *(__nv_bfloat16*)(smB + o * 128 + cl * 16 + wb) = l;
    }
    __syncthreads();

    const uint32_t sbB = smem_u32(smB);
    uint2* dst = (uint2*)g_bfrag4;
    for (int s = warp; s < 16; s += 4) {
        int ks = s >> 3, hl = (s >> 2) & 1, nt = s & 3;
        int r  = nt * 8 + (lane & 7);
        int c0 = hl * 4 + ks * 2 + ((lane >> 3) & 1);
        uint32_t f[2];
        ldsm2(f, sbB + r * 128 + (uint32_t)((c0 ^ (r & 7)) << 4));
        int g    = kl * 2 + ks;
        int fidx = hl * 4 + nt;
        dst[((((size_t)b * 18 + g) * 4 + (fidx >> 1)) * 32 + lane) * 2 + (fidx & 1)] =
            make_uint2(f[0], f[1]);
    }
}

// ---------------------------------------------------------------------------
// Conv mainloop. CTA = batch b, 8 output rows x 64 cols, all 32 Cout;
// 256 thr = 8 warps; warp w owns output row w (64 pixels = 4 m-tiles), so
// every B-fragment load feeds 48 MMAs. 2 CTAs/SM.
// A smem: 660 pixel-rows (10 halo rows x 66 halo cols) x 128B
//   [32 bf16 hi | 32 bf16 lo], 16B chunks XOR-swizzled by (p&7).
// Epilogue: warp-private smem transpose -> coalesced STG.128.
// ---------------------------------------------------------------------------
#define APIX   660                 // 10 * 66
#define ABYTES (APIX * 128)        // 84480
#define NTHR 256

__global__ void __launch_bounds__(NTHR, 2)
conv_mma(const float* __restrict__ x,
         float* __restrict__ out) {
    extern __shared__ __align__(128) char smA[];
    __shared__ float bfc[COUT];

    const int tid  = threadIdx.x;
    const int warp = tid >> 5;
    const int lane = tid & 31;
    const int b    = blockIdx.z;
    const int gy0  = blockIdx.y * 8;
    const int gx0  = blockIdx.x * 64;

    if (tid < COUT) bfc[tid] = g_bfinal[b * COUT + tid];

    // ---- Stage A: per pixel-row, 4 ci-octets -> 2x STS.128 each ----
    const float* xb = x + (size_t)b * CIN * HW;
    for (int p = tid; p < APIX; p += NTHR) {
        const int iy = p / 66;
        const int ix = p - iy * 66;
        const int gy = gy0 - 1 + iy;
        const int gx = gx0 - 1 + ix;
        const bool ok = (unsigned)gy < (unsigned)H_ && (unsigned)gx < (unsigned)W_;
        const float* px = xb + (size_t)(ok ? gy * W_ + gx : 0);
        char* arow = smA + p * 128;
        const int psw = p & 7;
#pragma unroll
        for (int c = 0; c < 4; c++) {
            float v[8];
#pragma unroll
            for (int j = 0; j < 8; j++)
                v[j] = ok ? px[(size_t)(8 * c + j) * HW] : 0.f;
            __nv_bfloat16 h[8];
            uint4 hv, lv;
#pragma unroll
            for (int j = 0; j < 8; j++) h[j] = __float2bfloat16(v[j]);
            hv.x = pack_bf2(h[0], h[1]);
            hv.y = pack_bf2(h[2], h[3]);
            hv.z = pack_bf2(h[4], h[5]);
            hv.w = pack_bf2(h[6], h[7]);
            __nv_bfloat16 l[8];
#pragma unroll
            for (int j = 0; j < 8; j++)
                l[j] = __float2bfloat16(v[j] - __bfloat162float(h[j]));
            lv.x = pack_bf2(l[0], l[1]);
            lv.y = pack_bf2(l[2], l[3]);
            lv.z = pack_bf2(l[4], l[5]);
            lv.w = pack_bf2(l[6], l[7]);
            *(uint4*)(arow + ((c ^ psw) << 4))       = hv;
            *(uint4*)(arow + (((c + 4) ^ psw) << 4)) = lv;
        }
    }
    __syncthreads();

    // ---- MMA mainloop: 4 m-tiles share every B-fragment load ----
    const uint32_t sbA = smem_u32(smA);
    const int kh = lane >> 4;
    const uint4* __restrict__ bfb = g_bfrag4 + (size_t)b * 18 * 4 * 32 + lane;

    // warp w owns output row w; m-tile t = cols [16t, 16t+16)
    const int pbase = warp * 66 + (lane & 15);

    float acc[4][4][4];
#pragma unroll
    for (int mt = 0; mt < 4; mt++)
#pragma unroll
        for (int nt = 0; nt < 4; nt++)
#pragma unroll
            for (int j = 0; j < 4; j++) acc[mt][nt][j] = 0.f;

#pragma unroll
    for (int tap = 0; tap < 9; tap++) {
        const int pshift = (tap / 3) * 66 + (tap % 3);
#pragma unroll
        for (int ks = 0; ks < 2; ks++) {
            const uint4* bp = bfb + (size_t)(tap * 2 + ks) * 4 * 32;
            uint4 q0 = bp[0 * 32];
            uint4 q1 = bp[1 * 32];
            uint4 q2 = bp[2 * 32];
            uint4 q3 = bp[3 * 32];

#pragma unroll
            for (int mt = 0; mt < 4; mt++) {
                const int pa = pbase + mt * 16 + pshift;
                const uint32_t arow = sbA + pa * 128;
                const int     psw  = pa & 7;
                uint32_t ah[4], al[4];
                ldsm4(ah, arow + (uint32_t)(((ks * 2 + kh)     ^ psw) << 4));
                ldsm4(al, arow + (uint32_t)(((4 + ks * 2 + kh) ^ psw) << 4));

                float* a0 = acc[mt][0];
                float* a1 = acc[mt][1];
                float* a2 = acc[mt][2];
                float* a3 = acc[mt][3];
                mma16816(a0, ah, q0.x, q0.y);
                mma16816(a0, al, q0.x, q0.y);
                mma16816(a0, ah, q2.x, q2.y);
                mma16816(a1, ah, q0.z, q0.w);
                mma16816(a1, al, q0.z, q0.w);
                mma16816(a1, ah, q2.z, q2.w);
                mma16816(a2, ah, q1.x, q1.y);
                mma16816(a2, al, q1.x, q1.y);
                mma16816(a2, ah, q3.x, q3.y);
                mma16816(a3, ah, q1.z, q1.w);
                mma16816(a3, al, q1.z, q1.w);
                mma16816(a3, ah, q3.z, q3.w);
            }
        }
    }

    // ---- Epilogue: warp-private smem transpose -> coalesced STG.128 ----
    __syncthreads();   // all warps done reading A tile
    float* scratch = (float*)smA + warp * 2048;   // 8KB per warp (64KB total)

#pragma unroll
    for (int mt = 0; mt < 4; mt++) {
#pragma unroll
        for (int nt = 0; nt < 4; nt++) {
#pragma unroll
            for (int j = 0; j < 4; j++) {
                int o   = nt * 8 + (lane & 3) * 2 + (j & 1);
                int pix = mt * 16 + (j >> 1) * 8 + (lane >> 2);
                scratch[o * 64 + pix] = acc[mt][nt][j] + bfc[o];
            }
        }
    }
    __syncwarp();

    const int gy = gy0 + warp;
    float* ob = out + (size_t)b * COUT * HW + (size_t)gy * W_ + gx0;
#pragma unroll
    for (int k = 0; k < 16; k++) {
        int o  = 2 * k + (lane >> 4);
        int xl = (lane & 15) * 4;
        float4 v = *(float4*)&scratch[o * 64 + xl];
        *(float4*)(ob + (size_t)o * HW + xl) = v;
    }
}

// ---------------------------------------------------------------------------
extern "C" void kernel_launch(void* const* d_in, const int* in_sizes, int n_in,
                              void* d_out, int out_size) {
    const float* x    = (const float*)d_in[0];
    const float* cond = (const float*)d_in[1];
    const float* lpe  = (const float*)d_in[2];
    const float* w    = (const float*)d_in[3];
    const float* bias = (const float*)d_in[4];
    const float* wa_w = (const float*)d_in[5];
    const float* wa_b = (const float*)d_in[6];
    const float* ba_w = (const float*)d_in[7];
    const float* ba_b = (const float*)d_in[8];
    float* out = (float*)d_out;

    cudaFuncSetAttribute(conv_mma,
                         cudaFuncAttributeMaxDynamicSharedMemorySize, ABYTES);

    prep_kernel<<<dim3(9, B_), 128>>>(cond, lpe, wa_w, wa_b, ba_w, ba_b, bias, w);

    dim3 grid(W_ / 64, H_ / 8, B_);
    conv_mma<<<grid, NTHR, ABYTES>>>(x, out);
}